// round 1
// baseline (speedup 1.0000x reference)
#include <cuda_runtime.h>
#include <math.h>

#define NY 1024
#define NX 1024
#define NSTEPS 64
#define NPTS (NY*NX)
#define NDX (NX-1)
#define NDY (NY-1)

__device__ float g_H[NPTS];
__device__ float g_Z[NPTS];
__device__ float g_smb[NPTS];
__device__ float g_D[NDY*NDX];
__device__ int   g_maxDbits[NSTEPS];
__device__ float g_time[NSTEPS+1];
__device__ float g_tlast[NSTEPS+1];

__device__ __forceinline__ float smb_of(float Zs, float precip, float mask,
                                        float tma_low, float tmj_low) {
    const float LAPSE = 0.0065f;
    const float MELTF = 0.5f;
    float T_ma = tma_low - LAPSE * Zs;
    float T_mj = tmj_low - LAPSE * Zs;
    float acc = precip * (T_ma < 0.0f ? 1.0f : 0.0f);
    float abl = MELTF * fmaxf(T_mj, 0.0f);
    return (acc - abl) * mask;
}

// ---------------------------------------------------------------------------
// Init: H=0, Z=Z_topo, smb=smb(Z_topo), scalars, zero per-step max slots.
// ---------------------------------------------------------------------------
__global__ void k_init(const float* __restrict__ Z_topo,
                       const float* __restrict__ precip,
                       const float* __restrict__ tma_p,
                       const float* __restrict__ tmj_p,
                       const float* __restrict__ mask) {
    int i = blockIdx.x * blockDim.x + threadIdx.x;
    int j = blockIdx.y * blockDim.y + threadIdx.y;
    if (i >= NX || j >= NY) return;
    int idx = j * NX + i;
    float zt = Z_topo[idx];
    g_H[idx] = 0.0f;
    g_Z[idx] = zt;
    g_smb[idx] = smb_of(zt, precip[idx], mask[idx], tma_p[0], tmj_p[0]);
    if (idx < NSTEPS) g_maxDbits[idx] = 0;
    if (idx == 0) { g_time[0] = 0.0f; g_tlast[0] = 0.0f; }
}

// ---------------------------------------------------------------------------
// Kernel A: staggered D field + global max(D) via per-block atomicMax.
// ---------------------------------------------------------------------------
__global__ void k_diff(int s) {
    int i = blockIdx.x * blockDim.x + threadIdx.x;   // 0..NDX-1
    int j = blockIdx.y * blockDim.y + threadIdx.y;   // 0..NDY-1
    float local = 0.0f;
    if (i < NDX && j < NDY) {
        int idx = j * NX + i;
        float h00 = g_H[idx],      h01 = g_H[idx + 1];
        float h10 = g_H[idx + NX], h11 = g_H[idx + NX + 1];
        float z00 = g_Z[idx],      z01 = g_Z[idx + 1];
        float z10 = g_Z[idx + NX], z11 = g_Z[idx + NX + 1];

        float H_avg = 0.25f * (h00 + h11 + h01 + h10);
        // slopes: divide before averaging (matches reference op order)
        float sx = 0.5f * ((z01 - z00) / 50.0f + (z11 - z10) / 50.0f);
        float sy = 0.5f * ((z10 - z00) / 50.0f + (z11 - z01) / 50.0f);
        float snorm = sqrtf(sx * sx + sy * sy + 1e-10f);

        const double RG = 910.0 * 9.81;
        const float CFACT = (float)(1e-17 * RG * RG * RG);
        float h2 = H_avg * H_avg;
        float h4 = h2 * h2;
        float h5 = h4 * H_avg;
        float D = CFACT * h5 * (snorm * snorm) + 1e-10f;
        g_D[j * NDX + i] = D;
        local = D;
    }
    // warp reduce
    #pragma unroll
    for (int o = 16; o > 0; o >>= 1)
        local = fmaxf(local, __shfl_xor_sync(0xFFFFFFFFu, local, o));
    __shared__ float wmax[8];
    int lane = threadIdx.x & 31;
    int wid  = (threadIdx.y * blockDim.x + threadIdx.x) >> 5;
    if (lane == 0) wmax[wid] = local;
    __syncthreads();
    if (wid == 0 && lane == 0) {
        int nw = (blockDim.x * blockDim.y) >> 5;
        float m = wmax[0];
        for (int w = 1; w < nw; w++) m = fmaxf(m, wmax[w]);
        atomicMax(&g_maxDbits[s], __float_as_int(m));   // D > 0 -> int order ok
    }
}

// ---------------------------------------------------------------------------
// Kernel C: dt (recomputed per thread), flux divergence, H/Z update,
// conditional SMB refresh, scalar advance, final-step output write.
// ---------------------------------------------------------------------------
__global__ void k_update(int s, int is_last,
                         const float* __restrict__ Z_topo,
                         const float* __restrict__ precip,
                         const float* __restrict__ tma_p,
                         const float* __restrict__ tmj_p,
                         const float* __restrict__ mask,
                         float* __restrict__ out) {
    int i = blockIdx.x * blockDim.x + threadIdx.x;
    int j = blockIdx.y * blockDim.y + threadIdx.y;
    if (i >= NX || j >= NY) return;

    float time  = g_time[s];
    float tlast = g_tlast[s];
    float maxD  = __int_as_float(g_maxDbits[s]);
    float dt = fminf(2500.0f / (2.7f * maxD), 0.5f);
    if (!(time < 32.0f)) dt = 0.0f;
    float tnew = time + dt;
    bool  upd  = (tnew - tlast) >= 5.0f;

    int idx = j * NX + i;
    float H  = g_H[idx];
    float Hn = H;
    if (i > 0 && i < NX - 1 && j > 0 && j < NY - 1) {
        int di = (j - 1) * NDX + (i - 1);
        float Dmm = g_D[di],       Dm0 = g_D[di + 1];        // D[j-1,i-1], D[j-1,i]
        float D0m = g_D[di + NDX], D00 = g_D[di + NDX + 1];  // D[j  ,i-1], D[j  ,i]

        float zc = g_Z[idx];
        float zl = g_Z[idx - 1],  zr = g_Z[idx + 1];
        float zu = g_Z[idx - NX], zd = g_Z[idx + NX];

        float qxr = -(0.5f * (Dm0 + D00)) * (zr - zc) / 50.0f;
        float qxl = -(0.5f * (Dmm + D0m)) * (zc - zl) / 50.0f;
        float qyd = -(0.5f * (D0m + D00)) * (zd - zc) / 50.0f;
        float qyu = -(0.5f * (Dmm + Dm0)) * (zc - zu) / 50.0f;
        float dHdt = -((qxr - qxl) / 50.0f + (qyd - qyu) / 50.0f);
        Hn = H + dt * (dHdt + g_smb[idx]);
    }
    Hn = fmaxf(Hn, 0.0f);
    float Zn = Z_topo[idx] + Hn;
    g_H[idx] = Hn;
    g_Z[idx] = Zn;
    if (upd)
        g_smb[idx] = smb_of(Zn, precip[idx], mask[idx], tma_p[0], tmj_p[0]);
    if (is_last) out[idx] = Hn;
    if (idx == 0) {
        g_time[s + 1]  = tnew;
        g_tlast[s + 1] = upd ? tnew : tlast;
    }
}

extern "C" void kernel_launch(void* const* d_in, const int* in_sizes, int n_in,
                              void* d_out, int out_size) {
    const float* precip = (const float*)d_in[0];
    const float* tma_p  = (const float*)d_in[1];
    const float* tmj_p  = (const float*)d_in[2];
    const float* Ztopo  = (const float*)d_in[3];
    const float* mask   = (const float*)d_in[4];
    float* out = (float*)d_out;

    dim3 blk(32, 8);
    dim3 grdFull((NX + 31) / 32, (NY + 7) / 8);
    dim3 grdStag((NDX + 31) / 32, (NDY + 7) / 8);

    k_init<<<grdFull, blk>>>(Ztopo, precip, tma_p, tmj_p, mask);
    for (int s = 0; s < NSTEPS; s++) {
        k_diff<<<grdStag, blk>>>(s);
        k_update<<<grdFull, blk>>>(s, (s == NSTEPS - 1) ? 1 : 0,
                                   Ztopo, precip, tma_p, tmj_p, mask, out);
    }
}